// round 6
// baseline (speedup 1.0000x reference)
#include <cuda_runtime.h>
#include <cuda_bf16.h>
#include <math_constants.h>

// Problem shapes (fixed for this problem instance)
#define N_FEAT   256
#define D_DIM    512
#define Q_BANK   2048
#define C_CLS    1000
#define IMG_ELEM 150528            // 3*224*224
#define IMG_VEC4 (IMG_ELEM/4)      // 37632
#define IMG_CHUNKS 147             // 37632 / 256
#define K_MAX    64

// Output layout (flattened, concatenated in reference return order, fp32)
#define OFF_LABELS 0
#define OFF_PROBS  (N_FEAT)
#define OFF_IMAGES (N_FEAT + N_FEAT*C_CLS)
#define OFF_GRADS  (N_FEAT + N_FEAT*C_CLS + (size_t)N_FEAT*IMG_ELEM)

// Device scratch (no cudaMalloc allowed)
__device__ float g_dist[N_FEAT * Q_BANK];   // 2 MB distance matrix
__device__ int   g_idx[N_FEAT * K_MAX];

__device__ __forceinline__ int read_k(const int* kp) {
    int k = kp ? kp[0] : 4;
    if (k < 1) k = 1;
    if (k > K_MAX) k = K_MAX;
    return k;
}

__device__ __forceinline__ void argmax_combine(float& v, int& i, float ov, int oi) {
    if (ov > v || (ov == v && oi < i)) { v = ov; i = oi; }
}

// ---------------------------------------------------------------------------
// Kernel 1: distance GEMM with fused L2 norms.
// dist[m][q] = 1 - dot(F[m], B[q]) / (|F[m]| * |B[q]|)
// 64x64 block tile, BK=16, 256 threads, 4x4 micro-tile, LDS.128-friendly
// padding, register double-buffered global loads. Row sums-of-squares are
// accumulated from the very same tile loads (each CTA sees the full K range
// of its row tiles), so no separate norms kernel is needed.
// ---------------------------------------------------------------------------
#define BM 64
#define BN 64
#define BK 16
__global__ __launch_bounds__(256) void dist_gemm_kernel(
        const float* __restrict__ A,    // features  (256 x 512)
        const float* __restrict__ B) {  // bank      (2048 x 512)
    __shared__ float As[BK][BM + 4];    // +4 keeps 16B alignment -> LDS.128
    __shared__ float Bs[BK][BN + 4];
    __shared__ float sqA[BM][4];
    __shared__ float sqB[BN][4];
    __shared__ float invA[BM];
    __shared__ float invB[BN];

    const int bm = blockIdx.y * BM;
    const int bn = blockIdx.x * BN;
    const int tid = threadIdx.x;
    const int ty = tid >> 4;       // 0..15 (m dir)
    const int tx = tid & 15;       // 0..15 (n dir)
    const int lr = tid >> 2;       // 0..63 load row
    const int lc = tid & 3;        // 0..3  float4 slot within BK

    const float* pA = A + (size_t)(bm + lr) * D_DIM + lc * 4;
    const float* pB = B + (size_t)(bn + lr) * D_DIM + lc * 4;

    float acc[4][4] = {};
    float sqa = 0.f, sqb = 0.f;

    float4 a = __ldg((const float4*)pA);
    float4 b = __ldg((const float4*)pB);

    for (int k0 = 0; k0 < D_DIM; k0 += BK) {
        As[lc * 4 + 0][lr] = a.x; As[lc * 4 + 1][lr] = a.y;
        As[lc * 4 + 2][lr] = a.z; As[lc * 4 + 3][lr] = a.w;
        Bs[lc * 4 + 0][lr] = b.x; Bs[lc * 4 + 1][lr] = b.y;
        Bs[lc * 4 + 2][lr] = b.z; Bs[lc * 4 + 3][lr] = b.w;
        sqa = fmaf(a.x, a.x, fmaf(a.y, a.y, fmaf(a.z, a.z, fmaf(a.w, a.w, sqa))));
        sqb = fmaf(b.x, b.x, fmaf(b.y, b.y, fmaf(b.z, b.z, fmaf(b.w, b.w, sqb))));
        __syncthreads();

        if (k0 + BK < D_DIM) {
            a = __ldg((const float4*)(pA + (k0 + BK)));
            b = __ldg((const float4*)(pB + (k0 + BK)));
        }

        #pragma unroll
        for (int kk = 0; kk < BK; kk++) {
            float4 rav = *reinterpret_cast<const float4*>(&As[kk][ty * 4]);
            float4 rbv = *reinterpret_cast<const float4*>(&Bs[kk][tx * 4]);
            float ra[4] = {rav.x, rav.y, rav.z, rav.w};
            float rb[4] = {rbv.x, rbv.y, rbv.z, rbv.w};
            #pragma unroll
            for (int i = 0; i < 4; i++)
                #pragma unroll
                for (int j = 0; j < 4; j++)
                    acc[i][j] = fmaf(ra[i], rb[j], acc[i][j]);
        }
        __syncthreads();
    }

    // reduce sums-of-squares -> inverse norms
    sqA[lr][lc] = sqa;
    sqB[lr][lc] = sqb;
    __syncthreads();
    if (tid < BM) {
        float s = sqA[tid][0] + sqA[tid][1] + sqA[tid][2] + sqA[tid][3];
        invA[tid] = 1.0f / fmaxf(sqrtf(s), 1e-12f);
    } else if (tid < BM + BN) {
        int r = tid - BM;
        float s = sqB[r][0] + sqB[r][1] + sqB[r][2] + sqB[r][3];
        invB[r] = 1.0f / fmaxf(sqrtf(s), 1e-12f);
    }
    __syncthreads();

    #pragma unroll
    for (int i = 0; i < 4; i++) {
        int m = bm + ty * 4 + i;
        float inf_m = invA[ty * 4 + i];
        #pragma unroll
        for (int j = 0; j < 4; j++) {
            int q = bn + tx * 4 + j;
            g_dist[(size_t)m * Q_BANK + q] = 1.0f - acc[i][j] * inf_m * invB[tx * 4 + j];
        }
    }
}

// ---------------------------------------------------------------------------
// Kernel 2: top-k (largest distance, ties -> lowest index), k argmax passes
// with warp-shuffle reductions. One block per feature row.
// ---------------------------------------------------------------------------
__global__ __launch_bounds__(256) void topk_kernel(const int* __restrict__ kp) {
    __shared__ float row[Q_BANK];
    __shared__ float wv[8];
    __shared__ int   wi[8];

    const int n = blockIdx.x;
    const int tid = threadIdx.x;
    const int lane = tid & 31;
    const int warp = tid >> 5;
    const int k = read_k(kp);

    #pragma unroll
    for (int i = tid; i < Q_BANK; i += 256) row[i] = g_dist[(size_t)n * Q_BANK + i];
    __syncthreads();

    for (int j = 0; j < k; j++) {
        float bv = -CUDART_INF_F;
        int   bi = 0x7fffffff;
        #pragma unroll
        for (int i = tid; i < Q_BANK; i += 256)
            argmax_combine(bv, bi, row[i], i);

        #pragma unroll
        for (int o = 16; o > 0; o >>= 1) {
            float ov = __shfl_down_sync(0xffffffffu, bv, o);
            int   oi = __shfl_down_sync(0xffffffffu, bi, o);
            argmax_combine(bv, bi, ov, oi);
        }
        if (lane == 0) { wv[warp] = bv; wi[warp] = bi; }
        __syncthreads();
        if (warp == 0) {
            float v = (lane < 8) ? wv[lane] : -CUDART_INF_F;
            int   i = (lane < 8) ? wi[lane] : 0x7fffffff;
            #pragma unroll
            for (int o = 4; o > 0; o >>= 1) {
                float ov = __shfl_down_sync(0xffffffffu, v, o);
                int   oi = __shfl_down_sync(0xffffffffu, i, o);
                argmax_combine(v, i, ov, oi);
            }
            if (lane == 0) {
                g_idx[n * K_MAX + j] = i;
                row[i] = -CUDART_INF_F;
            }
        }
        __syncthreads();
    }
}

// ---------------------------------------------------------------------------
// Kernel 3: fused gather. grid = (N_FEAT, 2 + IMG_CHUNKS)
//   blockIdx.y == 0 : grads_m row n           (mean of bank_features[idx])
//   blockIdx.y == 1 : pred_probs row n + label (mean of bank_probs[idx], argmax)
//   blockIdx.y >= 2 : pred_images chunk (y-2) of row n, float4
// Chunk-outer / n-inner launch order gives L2 reuse of repeated bank rows
// (per-chunk working set ~3 MB << 126 MB L2).
// ---------------------------------------------------------------------------
__global__ __launch_bounds__(256) void gather_kernel(
        const float* __restrict__ bankF,
        const float* __restrict__ bankP,
        const float* __restrict__ img,
        const int* __restrict__ kp,
        float* __restrict__ out_grads,
        float* __restrict__ out_probs,
        float* __restrict__ out_labels,
        float* __restrict__ out_images) {
    const int n   = blockIdx.x;
    const int y   = blockIdx.y;
    const int tid = threadIdx.x;
    const int k   = read_k(kp);
    const float fk = (float)k;

    if (y == 0) {
        // ---- grads_m: 512 floats = 128 float4 per row ----
        if (tid < 128) {
            float4 acc = make_float4(0.f, 0.f, 0.f, 0.f);
            for (int j = 0; j < k; j++) {
                const float4* src = reinterpret_cast<const float4*>(
                    bankF + (size_t)g_idx[n * K_MAX + j] * D_DIM);
                float4 v = __ldg(src + tid);
                acc.x += v.x; acc.y += v.y; acc.z += v.z; acc.w += v.w;
            }
            acc.x /= fk; acc.y /= fk; acc.z /= fk; acc.w /= fk;
            reinterpret_cast<float4*>(out_grads + (size_t)n * D_DIM)[tid] = acc;
        }
        return;
    }

    if (y == 1) {
        // ---- pred_probs (1000) + pred_labels ----
        __shared__ float wv[8];
        __shared__ int   wi[8];
        const int lane = tid & 31;
        const int warp = tid >> 5;

        int idxs[8];
        int kk = (k < 8) ? k : 8;
        for (int j = 0; j < kk; j++) idxs[j] = g_idx[n * K_MAX + j];

        float bv = -CUDART_INF_F;
        int   bc = 0x7fffffff;
        for (int c = tid; c < C_CLS; c += 256) {
            float s = 0.f;
            for (int j = 0; j < kk; j++)
                s += __ldg(bankP + (size_t)idxs[j] * C_CLS + c);
            for (int j = 8; j < k; j++)
                s += __ldg(bankP + (size_t)g_idx[n * K_MAX + j] * C_CLS + c);
            s = s / fk;
            out_probs[(size_t)n * C_CLS + c] = s;
            argmax_combine(bv, bc, s, c);
        }
        #pragma unroll
        for (int o = 16; o > 0; o >>= 1) {
            float ov = __shfl_down_sync(0xffffffffu, bv, o);
            int   oi = __shfl_down_sync(0xffffffffu, bc, o);
            argmax_combine(bv, bc, ov, oi);
        }
        if (lane == 0) { wv[warp] = bv; wi[warp] = bc; }
        __syncthreads();
        if (warp == 0) {
            float v = (lane < 8) ? wv[lane] : -CUDART_INF_F;
            int   i = (lane < 8) ? wi[lane] : 0x7fffffff;
            #pragma unroll
            for (int o = 4; o > 0; o >>= 1) {
                float ov = __shfl_down_sync(0xffffffffu, v, o);
                int   oi = __shfl_down_sync(0xffffffffu, i, o);
                argmax_combine(v, i, ov, oi);
            }
            if (lane == 0) out_labels[n] = (float)i;
        }
        return;
    }

    // ---- pred_images: chunk (y-2), 256 float4 per chunk ----
    const int e4 = (y - 2) * 256 + tid;   // < IMG_VEC4 by construction
    float4 acc = make_float4(0.f, 0.f, 0.f, 0.f);
    for (int j = 0; j < k; j++) {
        const float4* src = reinterpret_cast<const float4*>(
            img + (size_t)g_idx[n * K_MAX + j] * IMG_ELEM);
        float4 v = __ldg(src + e4);
        acc.x += v.x; acc.y += v.y; acc.z += v.z; acc.w += v.w;
    }
    acc.x /= fk; acc.y /= fk; acc.z /= fk; acc.w /= fk;
    reinterpret_cast<float4*>(out_images)[(size_t)n * IMG_VEC4 + e4] = acc;
}

// ---------------------------------------------------------------------------
extern "C" void kernel_launch(void* const* d_in, const int* in_sizes, int n_in,
                              void* d_out, int out_size) {
    const float* feat  = (const float*)d_in[0];   // (256, 512)
    const float* bankF = (const float*)d_in[1];   // (2048, 512)
    const float* bankP = (const float*)d_in[2];   // (2048, 1000)
    const float* img   = (const float*)d_in[3];   // (2048, 3, 224, 224)
    const int*   kp    = (n_in > 4) ? (const int*)d_in[4] : nullptr;

    float* out = (float*)d_out;
    float* out_labels = out + OFF_LABELS;
    float* out_probs  = out + OFF_PROBS;
    float* out_images = out + OFF_IMAGES;
    float* out_grads  = out + OFF_GRADS;

    // 1) distance GEMM (norms fused): grid (Q/64, N/64) = (32, 4)
    dim3 ggrid(Q_BANK / BN, N_FEAT / BM);
    dist_gemm_kernel<<<ggrid, 256>>>(feat, bankF);

    // 2) top-k
    topk_kernel<<<N_FEAT, 256>>>(kp);

    // 3) fused gather: grads / probs+labels / images
    dim3 fgrid(N_FEAT, 2 + IMG_CHUNKS);
    gather_kernel<<<fgrid, 256>>>(bankF, bankP, img, kp,
                                  out_grads, out_probs, out_labels, out_images);
}

// round 7
// speedup vs baseline: 1.0023x; 1.0023x over previous
#include <cuda_runtime.h>
#include <cuda_bf16.h>
#include <math_constants.h>

// Problem shapes (fixed for this problem instance)
#define N_FEAT   256
#define D_DIM    512
#define Q_BANK   2048
#define C_CLS    1000
#define IMG_ELEM 150528            // 3*224*224
#define IMG_VEC4 (IMG_ELEM/4)      // 37632
#define IMG_CHUNKS 147             // 37632 / 256
#define K_MAX    64

// Output layout (flattened, concatenated in reference return order, fp32)
#define OFF_LABELS 0
#define OFF_PROBS  (N_FEAT)
#define OFF_IMAGES (N_FEAT + N_FEAT*C_CLS)
#define OFF_GRADS  (N_FEAT + N_FEAT*C_CLS + (size_t)N_FEAT*IMG_ELEM)

// Device scratch (no cudaMalloc allowed)
__device__ float g_dist[N_FEAT * Q_BANK];   // 2 MB distance matrix
__device__ int   g_idx[N_FEAT * K_MAX];

__device__ __forceinline__ int read_k(const int* kp) {
    int k = kp ? kp[0] : 4;
    if (k < 1) k = 1;
    if (k > K_MAX) k = K_MAX;
    return k;
}

__device__ __forceinline__ void argmax_combine(float& v, int& i, float ov, int oi) {
    if (ov > v || (ov == v && oi < i)) { v = ov; i = oi; }
}

// ---------------------------------------------------------------------------
// Kernel 1: distance GEMM with fused L2 norms.
// dist[m][q] = 1 - dot(F[m], B[q]) / (|F[m]| * |B[q]|)
// 64x64 block tile, BK=16, 256 threads, 4x4 micro-tile, LDS.128-friendly
// padding, register double-buffered global loads. Row sums-of-squares are
// accumulated from the very same tile loads (each CTA sees the full K range
// of its row tiles), so no separate norms kernel is needed.
// ---------------------------------------------------------------------------
#define BM 64
#define BN 64
#define BK 16
__global__ __launch_bounds__(256) void dist_gemm_kernel(
        const float* __restrict__ A,    // features  (256 x 512)
        const float* __restrict__ B) {  // bank      (2048 x 512)
    __shared__ float As[BK][BM + 4];    // +4 keeps 16B alignment -> LDS.128
    __shared__ float Bs[BK][BN + 4];
    __shared__ float sqA[BM][4];
    __shared__ float sqB[BN][4];
    __shared__ float invA[BM];
    __shared__ float invB[BN];

    const int bm = blockIdx.y * BM;
    const int bn = blockIdx.x * BN;
    const int tid = threadIdx.x;
    const int ty = tid >> 4;       // 0..15 (m dir)
    const int tx = tid & 15;       // 0..15 (n dir)
    const int lr = tid >> 2;       // 0..63 load row
    const int lc = tid & 3;        // 0..3  float4 slot within BK

    const float* pA = A + (size_t)(bm + lr) * D_DIM + lc * 4;
    const float* pB = B + (size_t)(bn + lr) * D_DIM + lc * 4;

    float acc[4][4] = {};
    float sqa = 0.f, sqb = 0.f;

    float4 a = __ldg((const float4*)pA);
    float4 b = __ldg((const float4*)pB);

    for (int k0 = 0; k0 < D_DIM; k0 += BK) {
        As[lc * 4 + 0][lr] = a.x; As[lc * 4 + 1][lr] = a.y;
        As[lc * 4 + 2][lr] = a.z; As[lc * 4 + 3][lr] = a.w;
        Bs[lc * 4 + 0][lr] = b.x; Bs[lc * 4 + 1][lr] = b.y;
        Bs[lc * 4 + 2][lr] = b.z; Bs[lc * 4 + 3][lr] = b.w;
        sqa = fmaf(a.x, a.x, fmaf(a.y, a.y, fmaf(a.z, a.z, fmaf(a.w, a.w, sqa))));
        sqb = fmaf(b.x, b.x, fmaf(b.y, b.y, fmaf(b.z, b.z, fmaf(b.w, b.w, sqb))));
        __syncthreads();

        if (k0 + BK < D_DIM) {
            a = __ldg((const float4*)(pA + (k0 + BK)));
            b = __ldg((const float4*)(pB + (k0 + BK)));
        }

        #pragma unroll
        for (int kk = 0; kk < BK; kk++) {
            float4 rav = *reinterpret_cast<const float4*>(&As[kk][ty * 4]);
            float4 rbv = *reinterpret_cast<const float4*>(&Bs[kk][tx * 4]);
            float ra[4] = {rav.x, rav.y, rav.z, rav.w};
            float rb[4] = {rbv.x, rbv.y, rbv.z, rbv.w};
            #pragma unroll
            for (int i = 0; i < 4; i++)
                #pragma unroll
                for (int j = 0; j < 4; j++)
                    acc[i][j] = fmaf(ra[i], rb[j], acc[i][j]);
        }
        __syncthreads();
    }

    // reduce sums-of-squares -> inverse norms
    sqA[lr][lc] = sqa;
    sqB[lr][lc] = sqb;
    __syncthreads();
    if (tid < BM) {
        float s = sqA[tid][0] + sqA[tid][1] + sqA[tid][2] + sqA[tid][3];
        invA[tid] = 1.0f / fmaxf(sqrtf(s), 1e-12f);
    } else if (tid < BM + BN) {
        int r = tid - BM;
        float s = sqB[r][0] + sqB[r][1] + sqB[r][2] + sqB[r][3];
        invB[r] = 1.0f / fmaxf(sqrtf(s), 1e-12f);
    }
    __syncthreads();

    #pragma unroll
    for (int i = 0; i < 4; i++) {
        int m = bm + ty * 4 + i;
        float inf_m = invA[ty * 4 + i];
        #pragma unroll
        for (int j = 0; j < 4; j++) {
            int q = bn + tx * 4 + j;
            g_dist[(size_t)m * Q_BANK + q] = 1.0f - acc[i][j] * inf_m * invB[tx * 4 + j];
        }
    }
}

// ---------------------------------------------------------------------------
// Kernel 2: top-k (largest distance, ties -> lowest index), k argmax passes
// with warp-shuffle reductions. One block per feature row.
// ---------------------------------------------------------------------------
__global__ __launch_bounds__(256) void topk_kernel(const int* __restrict__ kp) {
    __shared__ float row[Q_BANK];
    __shared__ float wv[8];
    __shared__ int   wi[8];

    const int n = blockIdx.x;
    const int tid = threadIdx.x;
    const int lane = tid & 31;
    const int warp = tid >> 5;
    const int k = read_k(kp);

    #pragma unroll
    for (int i = tid; i < Q_BANK; i += 256) row[i] = g_dist[(size_t)n * Q_BANK + i];
    __syncthreads();

    for (int j = 0; j < k; j++) {
        float bv = -CUDART_INF_F;
        int   bi = 0x7fffffff;
        #pragma unroll
        for (int i = tid; i < Q_BANK; i += 256)
            argmax_combine(bv, bi, row[i], i);

        #pragma unroll
        for (int o = 16; o > 0; o >>= 1) {
            float ov = __shfl_down_sync(0xffffffffu, bv, o);
            int   oi = __shfl_down_sync(0xffffffffu, bi, o);
            argmax_combine(bv, bi, ov, oi);
        }
        if (lane == 0) { wv[warp] = bv; wi[warp] = bi; }
        __syncthreads();
        if (warp == 0) {
            float v = (lane < 8) ? wv[lane] : -CUDART_INF_F;
            int   i = (lane < 8) ? wi[lane] : 0x7fffffff;
            #pragma unroll
            for (int o = 4; o > 0; o >>= 1) {
                float ov = __shfl_down_sync(0xffffffffu, v, o);
                int   oi = __shfl_down_sync(0xffffffffu, i, o);
                argmax_combine(v, i, ov, oi);
            }
            if (lane == 0) {
                g_idx[n * K_MAX + j] = i;
                row[i] = -CUDART_INF_F;
            }
        }
        __syncthreads();
    }
}

// ---------------------------------------------------------------------------
// Kernel 3: fused gather. grid = (N_FEAT, 2 + IMG_CHUNKS)
//   blockIdx.y == 0 : grads_m row n           (mean of bank_features[idx])
//   blockIdx.y == 1 : pred_probs row n + label (mean of bank_probs[idx], argmax)
//   blockIdx.y >= 2 : pred_images chunk (y-2) of row n, float4
// Chunk-outer / n-inner launch order gives L2 reuse of repeated bank rows
// (per-chunk working set ~3 MB << 126 MB L2).
// ---------------------------------------------------------------------------
__global__ __launch_bounds__(256) void gather_kernel(
        const float* __restrict__ bankF,
        const float* __restrict__ bankP,
        const float* __restrict__ img,
        const int* __restrict__ kp,
        float* __restrict__ out_grads,
        float* __restrict__ out_probs,
        float* __restrict__ out_labels,
        float* __restrict__ out_images) {
    const int n   = blockIdx.x;
    const int y   = blockIdx.y;
    const int tid = threadIdx.x;
    const int k   = read_k(kp);
    const float fk = (float)k;

    if (y == 0) {
        // ---- grads_m: 512 floats = 128 float4 per row ----
        if (tid < 128) {
            float4 acc = make_float4(0.f, 0.f, 0.f, 0.f);
            for (int j = 0; j < k; j++) {
                const float4* src = reinterpret_cast<const float4*>(
                    bankF + (size_t)g_idx[n * K_MAX + j] * D_DIM);
                float4 v = __ldg(src + tid);
                acc.x += v.x; acc.y += v.y; acc.z += v.z; acc.w += v.w;
            }
            acc.x /= fk; acc.y /= fk; acc.z /= fk; acc.w /= fk;
            reinterpret_cast<float4*>(out_grads + (size_t)n * D_DIM)[tid] = acc;
        }
        return;
    }

    if (y == 1) {
        // ---- pred_probs (1000) + pred_labels ----
        __shared__ float wv[8];
        __shared__ int   wi[8];
        const int lane = tid & 31;
        const int warp = tid >> 5;

        int idxs[8];
        int kk = (k < 8) ? k : 8;
        for (int j = 0; j < kk; j++) idxs[j] = g_idx[n * K_MAX + j];

        float bv = -CUDART_INF_F;
        int   bc = 0x7fffffff;
        for (int c = tid; c < C_CLS; c += 256) {
            float s = 0.f;
            for (int j = 0; j < kk; j++)
                s += __ldg(bankP + (size_t)idxs[j] * C_CLS + c);
            for (int j = 8; j < k; j++)
                s += __ldg(bankP + (size_t)g_idx[n * K_MAX + j] * C_CLS + c);
            s = s / fk;
            out_probs[(size_t)n * C_CLS + c] = s;
            argmax_combine(bv, bc, s, c);
        }
        #pragma unroll
        for (int o = 16; o > 0; o >>= 1) {
            float ov = __shfl_down_sync(0xffffffffu, bv, o);
            int   oi = __shfl_down_sync(0xffffffffu, bc, o);
            argmax_combine(bv, bc, ov, oi);
        }
        if (lane == 0) { wv[warp] = bv; wi[warp] = bc; }
        __syncthreads();
        if (warp == 0) {
            float v = (lane < 8) ? wv[lane] : -CUDART_INF_F;
            int   i = (lane < 8) ? wi[lane] : 0x7fffffff;
            #pragma unroll
            for (int o = 4; o > 0; o >>= 1) {
                float ov = __shfl_down_sync(0xffffffffu, v, o);
                int   oi = __shfl_down_sync(0xffffffffu, i, o);
                argmax_combine(v, i, ov, oi);
            }
            if (lane == 0) out_labels[n] = (float)i;
        }
        return;
    }

    // ---- pred_images: chunk (y-2), 256 float4 per chunk ----
    const int e4 = (y - 2) * 256 + tid;   // < IMG_VEC4 by construction
    float4 acc = make_float4(0.f, 0.f, 0.f, 0.f);
    for (int j = 0; j < k; j++) {
        const float4* src = reinterpret_cast<const float4*>(
            img + (size_t)g_idx[n * K_MAX + j] * IMG_ELEM);
        float4 v = __ldg(src + e4);
        acc.x += v.x; acc.y += v.y; acc.z += v.z; acc.w += v.w;
    }
    acc.x /= fk; acc.y /= fk; acc.z /= fk; acc.w /= fk;
    reinterpret_cast<float4*>(out_images)[(size_t)n * IMG_VEC4 + e4] = acc;
}

// ---------------------------------------------------------------------------
extern "C" void kernel_launch(void* const* d_in, const int* in_sizes, int n_in,
                              void* d_out, int out_size) {
    const float* feat  = (const float*)d_in[0];   // (256, 512)
    const float* bankF = (const float*)d_in[1];   // (2048, 512)
    const float* bankP = (const float*)d_in[2];   // (2048, 1000)
    const float* img   = (const float*)d_in[3];   // (2048, 3, 224, 224)
    const int*   kp    = (n_in > 4) ? (const int*)d_in[4] : nullptr;

    float* out = (float*)d_out;
    float* out_labels = out + OFF_LABELS;
    float* out_probs  = out + OFF_PROBS;
    float* out_images = out + OFF_IMAGES;
    float* out_grads  = out + OFF_GRADS;

    // 1) distance GEMM (norms fused): grid (Q/64, N/64) = (32, 4)
    dim3 ggrid(Q_BANK / BN, N_FEAT / BM);
    dist_gemm_kernel<<<ggrid, 256>>>(feat, bankF);

    // 2) top-k
    topk_kernel<<<N_FEAT, 256>>>(kp);

    // 3) fused gather: grads / probs+labels / images
    dim3 fgrid(N_FEAT, 2 + IMG_CHUNKS);
    gather_kernel<<<fgrid, 256>>>(bankF, bankP, img, kp,
                                  out_grads, out_probs, out_labels, out_images);
}

// round 8
// speedup vs baseline: 1.0047x; 1.0023x over previous
#include <cuda_runtime.h>
#include <cuda_bf16.h>
#include <math_constants.h>

// Problem shapes (fixed for this problem instance)
#define N_FEAT   256
#define D_DIM    512
#define Q_BANK   2048
#define C_CLS    1000
#define IMG_ELEM 150528            // 3*224*224
#define IMG_VEC4 (IMG_ELEM/4)      // 37632
#define IMG_CHUNKS 147             // 37632 / 256
#define K_MAX    64

// Output layout (flattened, concatenated in reference return order, fp32)
#define OFF_LABELS 0
#define OFF_PROBS  (N_FEAT)
#define OFF_IMAGES (N_FEAT + N_FEAT*C_CLS)
#define OFF_GRADS  (N_FEAT + N_FEAT*C_CLS + (size_t)N_FEAT*IMG_ELEM)

// Device scratch (no cudaMalloc allowed)
__device__ float g_dist[N_FEAT * Q_BANK];   // 2 MB distance matrix
__device__ int   g_idx[N_FEAT * K_MAX];

__device__ __forceinline__ int read_k(const int* kp) {
    int k = kp ? kp[0] : 4;
    if (k < 1) k = 1;
    if (k > K_MAX) k = K_MAX;
    return k;
}

__device__ __forceinline__ void argmax_combine(float& v, int& i, float ov, int oi) {
    if (ov > v || (ov == v && oi < i)) { v = ov; i = oi; }
}

// ---------------------------------------------------------------------------
// Kernel 1: distance GEMM with fused L2 norms.
// dist[m][q] = 1 - dot(F[m], B[q]) / (|F[m]| * |B[q]|)
// 64x64 block tile, BK=16, 256 threads, 4x4 micro-tile, LDS.128-friendly
// padding, register double-buffered global loads. Row sums-of-squares are
// accumulated from the very same tile loads (each CTA sees the full K range
// of its row tiles), so no separate norms kernel is needed.
// ---------------------------------------------------------------------------
#define BM 64
#define BN 64
#define BK 16
__global__ __launch_bounds__(256) void dist_gemm_kernel(
        const float* __restrict__ A,    // features  (256 x 512)
        const float* __restrict__ B) {  // bank      (2048 x 512)
    __shared__ float As[BK][BM + 4];    // +4 keeps 16B alignment -> LDS.128
    __shared__ float Bs[BK][BN + 4];
    __shared__ float sqA[BM][4];
    __shared__ float sqB[BN][4];
    __shared__ float invA[BM];
    __shared__ float invB[BN];

    const int bm = blockIdx.y * BM;
    const int bn = blockIdx.x * BN;
    const int tid = threadIdx.x;
    const int ty = tid >> 4;       // 0..15 (m dir)
    const int tx = tid & 15;       // 0..15 (n dir)
    const int lr = tid >> 2;       // 0..63 load row
    const int lc = tid & 3;        // 0..3  float4 slot within BK

    const float* pA = A + (size_t)(bm + lr) * D_DIM + lc * 4;
    const float* pB = B + (size_t)(bn + lr) * D_DIM + lc * 4;

    float acc[4][4] = {};
    float sqa = 0.f, sqb = 0.f;

    float4 a = __ldg((const float4*)pA);
    float4 b = __ldg((const float4*)pB);

    for (int k0 = 0; k0 < D_DIM; k0 += BK) {
        As[lc * 4 + 0][lr] = a.x; As[lc * 4 + 1][lr] = a.y;
        As[lc * 4 + 2][lr] = a.z; As[lc * 4 + 3][lr] = a.w;
        Bs[lc * 4 + 0][lr] = b.x; Bs[lc * 4 + 1][lr] = b.y;
        Bs[lc * 4 + 2][lr] = b.z; Bs[lc * 4 + 3][lr] = b.w;
        sqa = fmaf(a.x, a.x, fmaf(a.y, a.y, fmaf(a.z, a.z, fmaf(a.w, a.w, sqa))));
        sqb = fmaf(b.x, b.x, fmaf(b.y, b.y, fmaf(b.z, b.z, fmaf(b.w, b.w, sqb))));
        __syncthreads();

        if (k0 + BK < D_DIM) {
            a = __ldg((const float4*)(pA + (k0 + BK)));
            b = __ldg((const float4*)(pB + (k0 + BK)));
        }

        #pragma unroll
        for (int kk = 0; kk < BK; kk++) {
            float4 rav = *reinterpret_cast<const float4*>(&As[kk][ty * 4]);
            float4 rbv = *reinterpret_cast<const float4*>(&Bs[kk][tx * 4]);
            float ra[4] = {rav.x, rav.y, rav.z, rav.w};
            float rb[4] = {rbv.x, rbv.y, rbv.z, rbv.w};
            #pragma unroll
            for (int i = 0; i < 4; i++)
                #pragma unroll
                for (int j = 0; j < 4; j++)
                    acc[i][j] = fmaf(ra[i], rb[j], acc[i][j]);
        }
        __syncthreads();
    }

    // reduce sums-of-squares -> inverse norms
    sqA[lr][lc] = sqa;
    sqB[lr][lc] = sqb;
    __syncthreads();
    if (tid < BM) {
        float s = sqA[tid][0] + sqA[tid][1] + sqA[tid][2] + sqA[tid][3];
        invA[tid] = 1.0f / fmaxf(sqrtf(s), 1e-12f);
    } else if (tid < BM + BN) {
        int r = tid - BM;
        float s = sqB[r][0] + sqB[r][1] + sqB[r][2] + sqB[r][3];
        invB[r] = 1.0f / fmaxf(sqrtf(s), 1e-12f);
    }
    __syncthreads();

    #pragma unroll
    for (int i = 0; i < 4; i++) {
        int m = bm + ty * 4 + i;
        float inf_m = invA[ty * 4 + i];
        #pragma unroll
        for (int j = 0; j < 4; j++) {
            int q = bn + tx * 4 + j;
            g_dist[(size_t)m * Q_BANK + q] = 1.0f - acc[i][j] * inf_m * invB[tx * 4 + j];
        }
    }
}

// ---------------------------------------------------------------------------
// Kernel 2: top-k (largest distance, ties -> lowest index), k argmax passes
// with warp-shuffle reductions. One block per feature row.
// ---------------------------------------------------------------------------
__global__ __launch_bounds__(256) void topk_kernel(const int* __restrict__ kp) {
    __shared__ float row[Q_BANK];
    __shared__ float wv[8];
    __shared__ int   wi[8];

    const int n = blockIdx.x;
    const int tid = threadIdx.x;
    const int lane = tid & 31;
    const int warp = tid >> 5;
    const int k = read_k(kp);

    #pragma unroll
    for (int i = tid; i < Q_BANK; i += 256) row[i] = g_dist[(size_t)n * Q_BANK + i];
    __syncthreads();

    for (int j = 0; j < k; j++) {
        float bv = -CUDART_INF_F;
        int   bi = 0x7fffffff;
        #pragma unroll
        for (int i = tid; i < Q_BANK; i += 256)
            argmax_combine(bv, bi, row[i], i);

        #pragma unroll
        for (int o = 16; o > 0; o >>= 1) {
            float ov = __shfl_down_sync(0xffffffffu, bv, o);
            int   oi = __shfl_down_sync(0xffffffffu, bi, o);
            argmax_combine(bv, bi, ov, oi);
        }
        if (lane == 0) { wv[warp] = bv; wi[warp] = bi; }
        __syncthreads();
        if (warp == 0) {
            float v = (lane < 8) ? wv[lane] : -CUDART_INF_F;
            int   i = (lane < 8) ? wi[lane] : 0x7fffffff;
            #pragma unroll
            for (int o = 4; o > 0; o >>= 1) {
                float ov = __shfl_down_sync(0xffffffffu, v, o);
                int   oi = __shfl_down_sync(0xffffffffu, i, o);
                argmax_combine(v, i, ov, oi);
            }
            if (lane == 0) {
                g_idx[n * K_MAX + j] = i;
                row[i] = -CUDART_INF_F;
            }
        }
        __syncthreads();
    }
}

// ---------------------------------------------------------------------------
// Kernel 3: fused gather. grid = (N_FEAT, 2 + IMG_CHUNKS)
//   blockIdx.y == 0 : grads_m row n           (mean of bank_features[idx])
//   blockIdx.y == 1 : pred_probs row n + label (mean of bank_probs[idx], argmax)
//   blockIdx.y >= 2 : pred_images chunk (y-2) of row n, float4
// Chunk-outer / n-inner launch order gives L2 reuse of repeated bank rows
// (per-chunk working set ~3 MB << 126 MB L2).
// ---------------------------------------------------------------------------
__global__ __launch_bounds__(256) void gather_kernel(
        const float* __restrict__ bankF,
        const float* __restrict__ bankP,
        const float* __restrict__ img,
        const int* __restrict__ kp,
        float* __restrict__ out_grads,
        float* __restrict__ out_probs,
        float* __restrict__ out_labels,
        float* __restrict__ out_images) {
    const int n   = blockIdx.x;
    const int y   = blockIdx.y;
    const int tid = threadIdx.x;
    const int k   = read_k(kp);
    const float fk = (float)k;

    if (y == 0) {
        // ---- grads_m: 512 floats = 128 float4 per row ----
        if (tid < 128) {
            float4 acc = make_float4(0.f, 0.f, 0.f, 0.f);
            for (int j = 0; j < k; j++) {
                const float4* src = reinterpret_cast<const float4*>(
                    bankF + (size_t)g_idx[n * K_MAX + j] * D_DIM);
                float4 v = __ldg(src + tid);
                acc.x += v.x; acc.y += v.y; acc.z += v.z; acc.w += v.w;
            }
            acc.x /= fk; acc.y /= fk; acc.z /= fk; acc.w /= fk;
            reinterpret_cast<float4*>(out_grads + (size_t)n * D_DIM)[tid] = acc;
        }
        return;
    }

    if (y == 1) {
        // ---- pred_probs (1000) + pred_labels ----
        __shared__ float wv[8];
        __shared__ int   wi[8];
        const int lane = tid & 31;
        const int warp = tid >> 5;

        int idxs[8];
        int kk = (k < 8) ? k : 8;
        for (int j = 0; j < kk; j++) idxs[j] = g_idx[n * K_MAX + j];

        float bv = -CUDART_INF_F;
        int   bc = 0x7fffffff;
        for (int c = tid; c < C_CLS; c += 256) {
            float s = 0.f;
            for (int j = 0; j < kk; j++)
                s += __ldg(bankP + (size_t)idxs[j] * C_CLS + c);
            for (int j = 8; j < k; j++)
                s += __ldg(bankP + (size_t)g_idx[n * K_MAX + j] * C_CLS + c);
            s = s / fk;
            out_probs[(size_t)n * C_CLS + c] = s;
            argmax_combine(bv, bc, s, c);
        }
        #pragma unroll
        for (int o = 16; o > 0; o >>= 1) {
            float ov = __shfl_down_sync(0xffffffffu, bv, o);
            int   oi = __shfl_down_sync(0xffffffffu, bc, o);
            argmax_combine(bv, bc, ov, oi);
        }
        if (lane == 0) { wv[warp] = bv; wi[warp] = bc; }
        __syncthreads();
        if (warp == 0) {
            float v = (lane < 8) ? wv[lane] : -CUDART_INF_F;
            int   i = (lane < 8) ? wi[lane] : 0x7fffffff;
            #pragma unroll
            for (int o = 4; o > 0; o >>= 1) {
                float ov = __shfl_down_sync(0xffffffffu, v, o);
                int   oi = __shfl_down_sync(0xffffffffu, i, o);
                argmax_combine(v, i, ov, oi);
            }
            if (lane == 0) out_labels[n] = (float)i;
        }
        return;
    }

    // ---- pred_images: chunk (y-2), 256 float4 per chunk ----
    const int e4 = (y - 2) * 256 + tid;   // < IMG_VEC4 by construction
    float4 acc = make_float4(0.f, 0.f, 0.f, 0.f);
    for (int j = 0; j < k; j++) {
        const float4* src = reinterpret_cast<const float4*>(
            img + (size_t)g_idx[n * K_MAX + j] * IMG_ELEM);
        float4 v = __ldg(src + e4);
        acc.x += v.x; acc.y += v.y; acc.z += v.z; acc.w += v.w;
    }
    acc.x /= fk; acc.y /= fk; acc.z /= fk; acc.w /= fk;
    reinterpret_cast<float4*>(out_images)[(size_t)n * IMG_VEC4 + e4] = acc;
}

// ---------------------------------------------------------------------------
extern "C" void kernel_launch(void* const* d_in, const int* in_sizes, int n_in,
                              void* d_out, int out_size) {
    const float* feat  = (const float*)d_in[0];   // (256, 512)
    const float* bankF = (const float*)d_in[1];   // (2048, 512)
    const float* bankP = (const float*)d_in[2];   // (2048, 1000)
    const float* img   = (const float*)d_in[3];   // (2048, 3, 224, 224)
    const int*   kp    = (n_in > 4) ? (const int*)d_in[4] : nullptr;

    float* out = (float*)d_out;
    float* out_labels = out + OFF_LABELS;
    float* out_probs  = out + OFF_PROBS;
    float* out_images = out + OFF_IMAGES;
    float* out_grads  = out + OFF_GRADS;

    // 1) distance GEMM (norms fused): grid (Q/64, N/64) = (32, 4)
    dim3 ggrid(Q_BANK / BN, N_FEAT / BM);
    dist_gemm_kernel<<<ggrid, 256>>>(feat, bankF);

    // 2) top-k
    topk_kernel<<<N_FEAT, 256>>>(kp);

    // 3) fused gather: grads / probs+labels / images
    dim3 fgrid(N_FEAT, 2 + IMG_CHUNKS);
    gather_kernel<<<fgrid, 256>>>(bankF, bankP, img, kp,
                                  out_grads, out_probs, out_labels, out_images);
}